// round 1
// baseline (speedup 1.0000x reference)
#include <cuda_runtime.h>
#include <math.h>

#define BB 8
#define NN 1000
#define CC 81
#define FG 80           // foreground classes
#define KK 100
#define MSZ 28
#define NPROB (BB*FG)   // 640
#define IMG_W 1216.0f
#define IMG_H 800.0f
#define SCORE_TH 0.05f
#define NMS_TH 0.5f
#define CLIPV 4.135166556742356f   // log(1000/16)

// ---- scratch (no allocations allowed) ----
__device__ int      g_cnt[NPROB];
__device__ float    g_score[NPROB*NN];
__device__ float    g_box[NPROB*NN*4];
__device__ unsigned g_nidx[NPROB*NN];
__device__ int      g_kept[NPROB*NN];
__device__ int      g_labels[BB*KK];

__global__ void k_zero() {
    int i = blockIdx.x * blockDim.x + threadIdx.x;
    if (i < NPROB) g_cnt[i] = 0;
}

// One warp per proposal row: softmax over 81 classes, threshold, decode box, append candidate.
__global__ void k_softmax_cand(const float* __restrict__ logits,
                               const float* __restrict__ reg,
                               const float* __restrict__ props) {
    int warp = (blockIdx.x * blockDim.x + threadIdx.x) >> 5;
    int lane = threadIdx.x & 31;
    if (warp >= BB * NN) return;
    int row = warp;
    const float* lg = logits + (size_t)row * CC;

    float mx = -3.402823466e38f;
    for (int c = lane; c < CC; c += 32) mx = fmaxf(mx, lg[c]);
    #pragma unroll
    for (int o = 16; o; o >>= 1) mx = fmaxf(mx, __shfl_xor_sync(0xFFFFFFFFu, mx, o));
    float sum = 0.f;
    for (int c = lane; c < CC; c += 32) sum += expf(lg[c] - mx);
    #pragma unroll
    for (int o = 16; o; o >>= 1) sum += __shfl_xor_sync(0xFFFFFFFFu, sum, o);

    float p0 = props[row*4+0], p1 = props[row*4+1];
    float p2 = props[row*4+2], p3 = props[row*4+3];
    float w = p2 - p0, h = p3 - p1;
    float cx = p0 + 0.5f * w, cy = p1 + 0.5f * h;
    int b = row / NN, n = row % NN;

    for (int c = 1 + lane; c < CC; c += 32) {
        float sc = expf(lg[c] - mx) / sum;
        if (sc > SCORE_TH) {
            const float* r = reg + (size_t)row * (CC*4) + c*4;
            float dx = r[0] / 10.0f, dy = r[1] / 10.0f;
            float dw = fminf(r[2] / 5.0f, CLIPV);
            float dh = fminf(r[3] / 5.0f, CLIPV);
            float pcx = dx * w + cx, pcy = dy * h + cy;
            float pw = expf(dw) * w, ph = expf(dh) * h;
            float x0 = fminf(fmaxf(pcx - 0.5f * pw, 0.f), IMG_W);
            float y0 = fminf(fmaxf(pcy - 0.5f * ph, 0.f), IMG_H);
            float x1 = fminf(fmaxf(pcx + 0.5f * pw, 0.f), IMG_W);
            float y1 = fminf(fmaxf(pcy + 0.5f * ph, 0.f), IMG_H);
            int prob = b * FG + (c - 1);
            int slot = atomicAdd(&g_cnt[prob], 1);   // slot < 1000 guaranteed
            int base = prob * NN + slot;
            g_score[base] = sc;
            g_box[base*4+0] = x0; g_box[base*4+1] = y0;
            g_box[base*4+2] = x1; g_box[base*4+3] = y1;
            g_nidx[base] = (unsigned)n;
        }
    }
}

// Per (image,class): sort candidates by (score desc, proposal idx asc), greedy NMS.
__global__ void k_nms() {
    int prob = blockIdx.x;
    int m = g_cnt[prob];
    if (m > NN) m = NN;
    __shared__ unsigned long long skey[1024];
    __shared__ int spay[1024];
    __shared__ float sx0[NN], sy0[NN], sx1[NN], sy1[NN], ssc[NN];
    __shared__ int skept[NN];
    int tid = threadIdx.x;

    for (int i = tid; i < 1024; i += blockDim.x) {
        if (i < m) {
            float sc = g_score[prob*NN + i];
            unsigned nb = g_nidx[prob*NN + i];
            skey[i] = ((unsigned long long)__float_as_uint(sc) << 32)
                    | (unsigned long long)(0xFFFFFFFFu - nb);
            spay[i] = i;
        } else { skey[i] = 0ull; spay[i] = 0; }
    }
    __syncthreads();

    // bitonic sort, descending (unique keys => deterministic)
    for (int k = 2; k <= 1024; k <<= 1) {
        for (int j = k >> 1; j > 0; j >>= 1) {
            for (int i = tid; i < 1024; i += blockDim.x) {
                int ix = i ^ j;
                if (ix > i) {
                    bool up = ((i & k) == 0);
                    unsigned long long a = skey[i], bk = skey[ix];
                    bool sw = up ? (a < bk) : (a > bk);
                    if (sw) {
                        skey[i] = bk; skey[ix] = a;
                        int t = spay[i]; spay[i] = spay[ix]; spay[ix] = t;
                    }
                }
            }
            __syncthreads();
        }
    }

    for (int i = tid; i < m; i += blockDim.x) {
        int p = prob*NN + spay[i];
        ssc[i] = __uint_as_float((unsigned)(skey[i] >> 32));
        sx0[i] = g_box[p*4+0]; sy0[i] = g_box[p*4+1];
        sx1[i] = g_box[p*4+2]; sy1[i] = g_box[p*4+3];
        skept[i] = 1;
    }
    __syncthreads();

    // greedy NMS: only surviving boxes suppress; forward only (matches reference)
    for (int i = 0; i < m; i++) {
        if (skept[i]) {
            float bx0 = sx0[i], by0 = sy0[i], bx1 = sx1[i], by1 = sy1[i];
            float a1 = (bx1 - bx0) * (by1 - by0);
            for (int j = i + 1 + tid; j < m; j += blockDim.x) {
                if (!skept[j]) continue;
                float lx = fmaxf(bx0, sx0[j]);
                float ly = fmaxf(by0, sy0[j]);
                float rx = fminf(bx1, sx1[j]);
                float ry = fminf(by1, sy1[j]);
                float iw = fmaxf(rx - lx, 0.f);
                float ih = fmaxf(ry - ly, 0.f);
                float inter = iw * ih;
                float a2 = (sx1[j] - sx0[j]) * (sy1[j] - sy0[j]);
                float iou = inter / (a1 + a2 - inter + 1e-9f);
                if (iou > NMS_TH) skept[j] = 0;
            }
        }
        __syncthreads();
    }

    for (int i = tid; i < m; i += blockDim.x) {
        int base = prob*NN + i;
        g_score[base] = ssc[i];
        g_box[base*4+0] = sx0[i]; g_box[base*4+1] = sy0[i];
        g_box[base*4+2] = sx1[i]; g_box[base*4+3] = sy1[i];
        g_kept[base] = skept[i];
    }
}

// Per image: top-100 over all kept candidates, tie-break = reference flat index c*N + sorted_pos.
#define CAP 4096
__global__ void k_topk(float* __restrict__ out) {
    int b = blockIdx.x;
    __shared__ unsigned long long keys[CAP];
    __shared__ int scnt;
    int tid = threadIdx.x;
    if (tid == 0) scnt = 0;
    __syncthreads();

    for (int c = 0; c < FG; c++) {
        int prob = b * FG + c;
        int m = g_cnt[prob];
        if (m > NN) m = NN;
        for (int i = tid; i < m; i += blockDim.x) {
            if (g_kept[prob*NN + i]) {
                int pos = atomicAdd(&scnt, 1);
                if (pos < CAP) {
                    unsigned fl = (unsigned)(c * NN + i);
                    keys[pos] = ((unsigned long long)__float_as_uint(g_score[prob*NN+i]) << 32)
                              | (unsigned long long)(0xFFFFFFFFu - fl);
                }
            }
        }
    }
    __syncthreads();
    int L = scnt < CAP ? scnt : CAP;
    for (int i = L + tid; i < CAP; i += blockDim.x) keys[i] = 0ull;
    __syncthreads();

    for (int k = 2; k <= CAP; k <<= 1) {
        for (int j = k >> 1; j > 0; j >>= 1) {
            for (int i = tid; i < CAP; i += blockDim.x) {
                int ix = i ^ j;
                if (ix > i) {
                    bool up = ((i & k) == 0);
                    unsigned long long a = keys[i], bk = keys[ix];
                    bool sw = up ? (a < bk) : (a > bk);
                    if (sw) { keys[i] = bk; keys[ix] = a; }
                }
            }
            __syncthreads();
        }
    }

    for (int k = tid; k < KK; k += blockDim.x) {
        unsigned long long key = keys[k];
        float sc = __uint_as_float((unsigned)(key >> 32));
        float x0 = 0.f, y0 = 0.f, x1 = 0.f, y1 = 0.f, scw = 0.f;
        int label = 0;
        if (sc > 0.0f) {
            unsigned fl = 0xFFFFFFFFu - (unsigned)(key & 0xFFFFFFFFull);
            int c = (int)(fl / NN), i = (int)(fl % NN);
            int base = (b * FG + c) * NN + i;
            x0 = g_box[base*4+0]; y0 = g_box[base*4+1];
            x1 = g_box[base*4+2]; y1 = g_box[base*4+3];
            scw = sc; label = c + 1;
        }
        int bk = b * KK + k;
        out[bk*4+0] = x0; out[bk*4+1] = y0; out[bk*4+2] = x1; out[bk*4+3] = y1;
        out[BB*KK*4 + bk] = scw;                 // top_s at 3200
        out[BB*KK*4 + BB*KK + bk] = (float)label;// labels at 4000
        g_labels[bk] = label;
    }
}

// Per detection: gather its class channel of mask logits, sigmoid.
__global__ void k_mask(const float* __restrict__ ml, float* __restrict__ out) {
    int bk = blockIdx.x;                 // b*K + k
    int label = g_labels[bk];
    const float* src = ml + ((size_t)bk * CC + (size_t)label) * (MSZ*MSZ);
    float* dst = out + (BB*KK*4 + 2*BB*KK) + (size_t)bk * (MSZ*MSZ);  // masks at 4800
    for (int t = threadIdx.x; t < MSZ*MSZ; t += blockDim.x) {
        float v = src[t];
        dst[t] = 1.0f / (1.0f + expf(-v));
    }
}

extern "C" void kernel_launch(void* const* d_in, const int* in_sizes, int n_in,
                              void* d_out, int out_size) {
    (void)in_sizes; (void)n_in; (void)out_size;
    const float* logits = (const float*)d_in[0];
    const float* reg    = (const float*)d_in[1];
    const float* props  = (const float*)d_in[2];
    const float* ml     = (const float*)d_in[3];
    float* out = (float*)d_out;

    k_zero<<<3, 256>>>();
    k_softmax_cand<<<(BB*NN + 7) / 8, 256>>>(logits, reg, props);
    k_nms<<<NPROB, 256>>>();
    k_topk<<<BB, 512>>>(out);
    k_mask<<<BB*KK, 128>>>(ml, out);
}

// round 4
// speedup vs baseline: 2.1085x; 2.1085x over previous
#include <cuda_runtime.h>
#include <math.h>

#define BB 8
#define NN 1000
#define CC 81
#define FG 80           // foreground classes
#define KK 100
#define MSZ 28
#define NPROB (BB*FG)   // 640
#define IMG_W 1216.0f
#define IMG_H 800.0f
#define SCORE_TH 0.05f
#define NMS_TH 0.5f
#define CLIPV 4.135166556742356f   // log(1000/16)
#define CAP 4096

// ---- scratch (no allocations allowed) ----
__device__ int                g_cnt[NPROB];          // candidates per (b,c)
__device__ int                g_kcnt[NPROB];         // kept after NMS per (b,c)
__device__ float              g_score[NPROB*NN];
__device__ float              g_box[NPROB*NN*4];
__device__ unsigned           g_nidx[NPROB*NN];
__device__ unsigned long long g_keys[NPROB*NN];      // compacted kept keys
__device__ int                g_labels[BB*KK];

__global__ void k_zero() {
    int i = threadIdx.x;
    if (i < NPROB) { g_cnt[i] = 0; g_kcnt[i] = 0; }
}

// One warp per proposal row: softmax over 81 classes (register-cached),
// threshold, decode box, append candidate.
__global__ void k_softmax_cand(const float* __restrict__ logits,
                               const float* __restrict__ reg,
                               const float* __restrict__ props) {
    int warp = (blockIdx.x * blockDim.x + threadIdx.x) >> 5;
    int lane = threadIdx.x & 31;
    if (warp >= BB * NN) return;
    int row = warp;
    const float* lg = logits + (size_t)row * CC;

    // cache logits: c = lane, lane+32, lane+64
    float v0 = lg[lane];
    float v1 = lg[lane + 32];
    float v2 = (lane + 64 < CC) ? lg[lane + 64] : -3.402823466e38f;

    float mx = fmaxf(fmaxf(v0, v1), v2);
    #pragma unroll
    for (int o = 16; o; o >>= 1) mx = fmaxf(mx, __shfl_xor_sync(0xFFFFFFFFu, mx, o));
    float e0 = expf(v0 - mx), e1 = expf(v1 - mx);
    float e2 = (lane + 64 < CC) ? expf(v2 - mx) : 0.f;
    float sum = e0 + e1 + e2;
    #pragma unroll
    for (int o = 16; o; o >>= 1) sum += __shfl_xor_sync(0xFFFFFFFFu, sum, o);
    float inv = 1.0f / sum;

    float p0 = props[row*4+0], p1 = props[row*4+1];
    float p2 = props[row*4+2], p3 = props[row*4+3];
    float w = p2 - p0, h = p3 - p1;
    float cx = p0 + 0.5f * w, cy = p1 + 0.5f * h;
    int b = row / NN, n = row % NN;

    #pragma unroll
    for (int u = 0; u < 3; u++) {
        int c = lane + u * 32;
        if (c == 0 || c >= CC) continue;
        float sc = (u == 0 ? e0 : (u == 1 ? e1 : e2)) * inv;
        if (sc > SCORE_TH) {
            const float* r = reg + (size_t)row * (CC*4) + c*4;
            float dx = r[0] * 0.1f, dy = r[1] * 0.1f;
            float dw = fminf(r[2] * 0.2f, CLIPV);
            float dh = fminf(r[3] * 0.2f, CLIPV);
            float pcx = dx * w + cx, pcy = dy * h + cy;
            float pw = expf(dw) * w, ph = expf(dh) * h;
            float x0 = fminf(fmaxf(pcx - 0.5f * pw, 0.f), IMG_W);
            float y0 = fminf(fmaxf(pcy - 0.5f * ph, 0.f), IMG_H);
            float x1 = fminf(fmaxf(pcx + 0.5f * pw, 0.f), IMG_W);
            float y1 = fminf(fmaxf(pcy + 0.5f * ph, 0.f), IMG_H);
            int prob = b * FG + (c - 1);
            int slot = atomicAdd(&g_cnt[prob], 1);
            int base = prob * NN + slot;
            g_score[base] = sc;
            g_box[base*4+0] = x0; g_box[base*4+1] = y0;
            g_box[base*4+2] = x1; g_box[base*4+3] = y1;
            g_nidx[base] = (unsigned)n;
        }
    }
}

// Per (image,class): sort candidates by (score desc, proposal idx asc) over
// next_pow2(m) elements, greedy NMS, compact kept keys to g_keys.
__global__ void k_nms() {
    int prob = blockIdx.x;
    int c = prob % FG;
    int m = g_cnt[prob];
    if (m > NN) m = NN;
    __shared__ unsigned long long skey[1024];
    __shared__ int spay[1024];
    __shared__ float sx0[NN], sy0[NN], sx1[NN], sy1[NN], ssc[NN];
    __shared__ int skept[NN];
    int tid = threadIdx.x;

    int n2 = 32; while (n2 < m) n2 <<= 1;   // m<=1000 -> n2<=1024

    for (int i = tid; i < n2; i += blockDim.x) {
        if (i < m) {
            float sc = g_score[prob*NN + i];
            unsigned nb = g_nidx[prob*NN + i];
            skey[i] = ((unsigned long long)__float_as_uint(sc) << 32)
                    | (unsigned long long)(0xFFFFFFFFu - nb);
            spay[i] = i;
        } else { skey[i] = 0ull; spay[i] = 0; }
    }
    __syncthreads();

    for (int k = 2; k <= n2; k <<= 1) {
        for (int j = k >> 1; j > 0; j >>= 1) {
            for (int i = tid; i < n2; i += blockDim.x) {
                int ix = i ^ j;
                if (ix > i) {
                    bool up = ((i & k) == 0);
                    unsigned long long a = skey[i], bk = skey[ix];
                    bool sw = up ? (a < bk) : (a > bk);
                    if (sw) {
                        skey[i] = bk; skey[ix] = a;
                        int t = spay[i]; spay[i] = spay[ix]; spay[ix] = t;
                    }
                }
            }
            __syncthreads();
        }
    }

    for (int i = tid; i < m; i += blockDim.x) {
        int p = prob*NN + spay[i];
        ssc[i] = __uint_as_float((unsigned)(skey[i] >> 32));
        sx0[i] = g_box[p*4+0]; sy0[i] = g_box[p*4+1];
        sx1[i] = g_box[p*4+2]; sy1[i] = g_box[p*4+3];
        skept[i] = 1;
    }
    __syncthreads();

    // greedy NMS: only surviving boxes suppress; forward only (matches reference)
    for (int i = 0; i < m; i++) {
        if (skept[i]) {
            float bx0 = sx0[i], by0 = sy0[i], bx1 = sx1[i], by1 = sy1[i];
            float a1 = (bx1 - bx0) * (by1 - by0);
            for (int j = i + 1 + tid; j < m; j += blockDim.x) {
                if (!skept[j]) continue;
                float lx = fmaxf(bx0, sx0[j]);
                float ly = fmaxf(by0, sy0[j]);
                float rx = fminf(bx1, sx1[j]);
                float ry = fminf(by1, sy1[j]);
                float iw = fmaxf(rx - lx, 0.f);
                float ih = fmaxf(ry - ly, 0.f);
                float inter = iw * ih;
                float a2 = (sx1[j] - sx0[j]) * (sy1[j] - sy0[j]);
                float iou = inter / (a1 + a2 - inter + 1e-9f);
                if (iou > NMS_TH) skept[j] = 0;
            }
        }
        __syncthreads();
    }

    // write sorted boxes back (topk dereferences by sorted position),
    // compact kept keys (order within list irrelevant: keys unique, sorted later)
    for (int i = tid; i < m; i += blockDim.x) {
        int base = prob*NN + i;
        g_box[base*4+0] = sx0[i]; g_box[base*4+1] = sy0[i];
        g_box[base*4+2] = sx1[i]; g_box[base*4+3] = sy1[i];
        if (skept[i]) {
            int pos = atomicAdd(&g_kcnt[prob], 1);
            unsigned fl = (unsigned)(c * NN + i);
            g_keys[prob*NN + pos] =
                ((unsigned long long)__float_as_uint(ssc[i]) << 32)
              | (unsigned long long)(0xFFFFFFFFu - fl);
        }
    }
}

// Per image: gather per-class kept keys via prefix offsets, bitonic sort
// next_pow2(L), emit top-100 with boxes/scores/labels.
__global__ void k_topk(float* __restrict__ out) {
    int b = blockIdx.x;
    __shared__ unsigned long long keys[CAP];
    __shared__ int scnt[FG];
    __shared__ int soff[FG + 1];
    int tid = threadIdx.x;
    int lane = tid & 31;
    int wid = tid >> 5;           // 32 warps @ 1024 threads

    if (tid < FG) scnt[tid] = min(g_kcnt[b * FG + tid], NN);
    __syncthreads();
    if (tid == 0) {
        int acc = 0;
        for (int c2 = 0; c2 < FG; c2++) { soff[c2] = acc; acc += scnt[c2]; }
        soff[FG] = acc;
    }
    __syncthreads();
    int L = soff[FG]; if (L > CAP) L = CAP;

    // warp w copies classes w, w+32, w+64
    for (int c2 = wid; c2 < FG; c2 += 32) {
        int off = soff[c2], cnt = scnt[c2];
        const unsigned long long* src = g_keys + (size_t)(b * FG + c2) * NN;
        for (int i = lane; i < cnt; i += 32) {
            int d = off + i;
            if (d < CAP) keys[d] = src[i];
        }
    }
    __syncthreads();

    int n2 = 128; while (n2 < L) n2 <<= 1;   // >= KK, <= CAP
    for (int i = L + tid; i < n2; i += blockDim.x) keys[i] = 0ull;
    __syncthreads();

    for (int k = 2; k <= n2; k <<= 1) {
        for (int j = k >> 1; j > 0; j >>= 1) {
            for (int i = tid; i < n2; i += blockDim.x) {
                int ix = i ^ j;
                if (ix > i) {
                    bool up = ((i & k) == 0);
                    unsigned long long a = keys[i], bk = keys[ix];
                    bool sw = up ? (a < bk) : (a > bk);
                    if (sw) { keys[i] = bk; keys[ix] = a; }
                }
            }
            __syncthreads();
        }
    }

    if (tid < KK) {
        int k = tid;
        unsigned long long key = keys[k];
        float sc = __uint_as_float((unsigned)(key >> 32));
        float x0 = 0.f, y0 = 0.f, x1 = 0.f, y1 = 0.f, scw = 0.f;
        int label = 0;
        if (sc > 0.0f) {
            unsigned fl = 0xFFFFFFFFu - (unsigned)(key & 0xFFFFFFFFull);
            int c2 = (int)(fl / NN), i = (int)(fl % NN);
            int base = (b * FG + c2) * NN + i;
            x0 = g_box[base*4+0]; y0 = g_box[base*4+1];
            x1 = g_box[base*4+2]; y1 = g_box[base*4+3];
            scw = sc; label = c2 + 1;
        }
        int bk = b * KK + k;
        out[bk*4+0] = x0; out[bk*4+1] = y0; out[bk*4+2] = x1; out[bk*4+3] = y1;
        out[BB*KK*4 + bk] = scw;                  // top_s at 3200
        out[BB*KK*4 + BB*KK + bk] = (float)label; // labels at 4000
        g_labels[bk] = label;
    }
}

// Per detection: gather its class channel of mask logits, sigmoid (float4-vectorized).
__global__ void k_mask(const float* __restrict__ ml, float* __restrict__ out) {
    int bk = blockIdx.x;                 // b*K + k
    int label = g_labels[bk];
    const float4* src = (const float4*)(ml + ((size_t)bk * CC + (size_t)label) * (MSZ*MSZ));
    float4* dst = (float4*)(out + (BB*KK*4 + 2*BB*KK) + (size_t)bk * (MSZ*MSZ));
    for (int t = threadIdx.x; t < (MSZ*MSZ)/4; t += blockDim.x) {
        float4 v = src[t];
        v.x = 1.0f / (1.0f + expf(-v.x));
        v.y = 1.0f / (1.0f + expf(-v.y));
        v.z = 1.0f / (1.0f + expf(-v.z));
        v.w = 1.0f / (1.0f + expf(-v.w));
        dst[t] = v;
    }
}

extern "C" void kernel_launch(void* const* d_in, const int* in_sizes, int n_in,
                              void* d_out, int out_size) {
    (void)in_sizes; (void)n_in; (void)out_size;
    const float* logits = (const float*)d_in[0];
    const float* reg    = (const float*)d_in[1];
    const float* props  = (const float*)d_in[2];
    const float* ml     = (const float*)d_in[3];
    float* out = (float*)d_out;

    k_zero<<<1, NPROB>>>();
    k_softmax_cand<<<(BB*NN + 7) / 8, 256>>>(logits, reg, props);
    k_nms<<<NPROB, 256>>>();
    k_topk<<<BB, 1024>>>(out);
    k_mask<<<BB*KK, 196>>>(ml, out);
}

// round 5
// speedup vs baseline: 4.0887x; 1.9392x over previous
#include <cuda_runtime.h>
#include <math.h>

#define BB 8
#define NN 1000
#define CC 81
#define FG 80           // foreground classes
#define KK 100
#define MSZ 28
#define NPROB (BB*FG)   // 640
#define IMG_W 1216.0f
#define IMG_H 800.0f
#define SCORE_TH 0.05f
#define NMS_TH 0.5f
#define CLIPV 4.135166556742356f   // log(1000/16)
#define CAP 4096
#define NB 1024         // select histogram bins
#define CB 512          // collect buffer cap
#define BIN_BASE 0x3D4C // float bits top-16 of 0.05

// ---- scratch (no allocations allowed) ----
__device__ int                g_cnt[NPROB];          // candidates per (b,c)
__device__ int                g_kcnt[NPROB];         // kept after NMS per (b,c)
__device__ float              g_score[NPROB*NN];
__device__ float              g_box[NPROB*NN*4];
__device__ unsigned           g_nidx[NPROB*NN];
__device__ unsigned long long g_keys[NPROB*NN];      // compacted kept keys
__device__ int                g_labels[BB*KK];

// One warp per proposal row: softmax over 81 classes (register-cached),
// threshold, decode box, append candidate.
__global__ void k_softmax_cand(const float* __restrict__ logits,
                               const float* __restrict__ reg,
                               const float* __restrict__ props) {
    int warp = (blockIdx.x * blockDim.x + threadIdx.x) >> 5;
    int lane = threadIdx.x & 31;
    if (warp >= BB * NN) return;
    int row = warp;
    const float* lg = logits + (size_t)row * CC;

    float v0 = lg[lane];
    float v1 = lg[lane + 32];
    float v2 = (lane + 64 < CC) ? lg[lane + 64] : -3.402823466e38f;

    float mx = fmaxf(fmaxf(v0, v1), v2);
    #pragma unroll
    for (int o = 16; o; o >>= 1) mx = fmaxf(mx, __shfl_xor_sync(0xFFFFFFFFu, mx, o));
    float e0 = expf(v0 - mx), e1 = expf(v1 - mx);
    float e2 = (lane + 64 < CC) ? expf(v2 - mx) : 0.f;
    float sum = e0 + e1 + e2;
    #pragma unroll
    for (int o = 16; o; o >>= 1) sum += __shfl_xor_sync(0xFFFFFFFFu, sum, o);
    float inv = 1.0f / sum;

    float p0 = props[row*4+0], p1 = props[row*4+1];
    float p2 = props[row*4+2], p3 = props[row*4+3];
    float w = p2 - p0, h = p3 - p1;
    float cx = p0 + 0.5f * w, cy = p1 + 0.5f * h;
    int b = row / NN, n = row % NN;

    #pragma unroll
    for (int u = 0; u < 3; u++) {
        int c = lane + u * 32;
        if (c == 0 || c >= CC) continue;
        float sc = (u == 0 ? e0 : (u == 1 ? e1 : e2)) * inv;
        if (sc > SCORE_TH) {
            const float* r = reg + (size_t)row * (CC*4) + c*4;
            float dx = r[0] * 0.1f, dy = r[1] * 0.1f;
            float dw = fminf(r[2] * 0.2f, CLIPV);
            float dh = fminf(r[3] * 0.2f, CLIPV);
            float pcx = dx * w + cx, pcy = dy * h + cy;
            float pw = expf(dw) * w, ph = expf(dh) * h;
            float x0 = fminf(fmaxf(pcx - 0.5f * pw, 0.f), IMG_W);
            float y0 = fminf(fmaxf(pcy - 0.5f * ph, 0.f), IMG_H);
            float x1 = fminf(fmaxf(pcx + 0.5f * pw, 0.f), IMG_W);
            float y1 = fminf(fmaxf(pcy + 0.5f * ph, 0.f), IMG_H);
            int prob = b * FG + (c - 1);
            int slot = atomicAdd(&g_cnt[prob], 1);
            int base = prob * NN + slot;
            g_score[base] = sc;
            g_box[base*4+0] = x0; g_box[base*4+1] = y0;
            g_box[base*4+2] = x1; g_box[base*4+3] = y1;
            g_nidx[base] = (unsigned)n;
        }
    }
}

// Per (image,class): sort candidates by (score desc, proposal idx asc) over
// next_pow2(m) elements, greedy NMS, compact kept keys to g_keys.
// Re-zeroes g_cnt[prob] at the end so the next replay starts clean.
__global__ void k_nms() {
    int prob = blockIdx.x;
    int c = prob % FG;
    int m = g_cnt[prob];
    if (m > NN) m = NN;
    __shared__ unsigned long long skey[1024];
    __shared__ int spay[1024];
    __shared__ float sx0[NN], sy0[NN], sx1[NN], sy1[NN], ssc[NN];
    __shared__ int skept[NN];
    int tid = threadIdx.x;

    int n2 = 32; while (n2 < m) n2 <<= 1;   // m<=1000 -> n2<=1024

    for (int i = tid; i < n2; i += blockDim.x) {
        if (i < m) {
            float sc = g_score[prob*NN + i];
            unsigned nb = g_nidx[prob*NN + i];
            skey[i] = ((unsigned long long)__float_as_uint(sc) << 32)
                    | (unsigned long long)(0xFFFFFFFFu - nb);
            spay[i] = i;
        } else { skey[i] = 0ull; spay[i] = 0; }
    }
    __syncthreads();

    for (int k = 2; k <= n2; k <<= 1) {
        for (int j = k >> 1; j > 0; j >>= 1) {
            for (int i = tid; i < n2; i += blockDim.x) {
                int ix = i ^ j;
                if (ix > i) {
                    bool up = ((i & k) == 0);
                    unsigned long long a = skey[i], bk = skey[ix];
                    bool sw = up ? (a < bk) : (a > bk);
                    if (sw) {
                        skey[i] = bk; skey[ix] = a;
                        int t = spay[i]; spay[i] = spay[ix]; spay[ix] = t;
                    }
                }
            }
            __syncthreads();
        }
    }

    for (int i = tid; i < m; i += blockDim.x) {
        int p = prob*NN + spay[i];
        ssc[i] = __uint_as_float((unsigned)(skey[i] >> 32));
        sx0[i] = g_box[p*4+0]; sy0[i] = g_box[p*4+1];
        sx1[i] = g_box[p*4+2]; sy1[i] = g_box[p*4+3];
        skept[i] = 1;
    }
    __syncthreads();

    // greedy NMS: only surviving boxes suppress; forward only (matches reference)
    for (int i = 0; i < m; i++) {
        if (skept[i]) {
            float bx0 = sx0[i], by0 = sy0[i], bx1 = sx1[i], by1 = sy1[i];
            float a1 = (bx1 - bx0) * (by1 - by0);
            for (int j = i + 1 + tid; j < m; j += blockDim.x) {
                if (!skept[j]) continue;
                float lx = fmaxf(bx0, sx0[j]);
                float ly = fmaxf(by0, sy0[j]);
                float rx = fminf(bx1, sx1[j]);
                float ry = fminf(by1, sy1[j]);
                float iw = fmaxf(rx - lx, 0.f);
                float ih = fmaxf(ry - ly, 0.f);
                float inter = iw * ih;
                float a2 = (sx1[j] - sx0[j]) * (sy1[j] - sy0[j]);
                float iou = inter / (a1 + a2 - inter + 1e-9f);
                if (iou > NMS_TH) skept[j] = 0;
            }
        }
        __syncthreads();
    }

    for (int i = tid; i < m; i += blockDim.x) {
        int base = prob*NN + i;
        g_box[base*4+0] = sx0[i]; g_box[base*4+1] = sy0[i];
        g_box[base*4+2] = sx1[i]; g_box[base*4+3] = sy1[i];
        if (skept[i]) {
            int pos = atomicAdd(&g_kcnt[prob], 1);
            unsigned fl = (unsigned)(c * NN + i);
            g_keys[prob*NN + pos] =
                ((unsigned long long)__float_as_uint(ssc[i]) << 32)
              | (unsigned long long)(0xFFFFFFFFu - fl);
        }
    }
    if (tid == 0) g_cnt[prob] = 0;   // reset for next replay
}

__device__ __forceinline__ void bitonic_desc(unsigned long long* a, int n2, int tid, int nthr) {
    for (int k = 2; k <= n2; k <<= 1) {
        for (int j = k >> 1; j > 0; j >>= 1) {
            for (int i = tid; i < n2; i += nthr) {
                int ix = i ^ j;
                if (ix > i) {
                    bool up = ((i & k) == 0);
                    unsigned long long x = a[i], y = a[ix];
                    bool sw = up ? (x < y) : (x > y);
                    if (sw) { a[i] = y; a[ix] = x; }
                }
            }
            __syncthreads();
        }
    }
}

// Per image: gather per-class kept keys, radix-select the top ~K by score
// high-bits, sort only the selected set, emit top-100. Fallback: full sort.
__global__ void k_topk(float* __restrict__ out) {
    int b = blockIdx.x;
    __shared__ unsigned long long keys[CAP];
    __shared__ unsigned long long cbuf[CB];
    __shared__ int hist[NB];
    __shared__ int scnt[FG];
    __shared__ int soff[FG + 1];
    __shared__ int sth, sccnt;
    int tid = threadIdx.x;
    int lane = tid & 31;
    int wid = tid >> 5;           // 32 warps @ 1024 threads

    if (tid < FG) {
        int p = b * FG + tid;
        scnt[tid] = min(g_kcnt[p], NN);
        g_kcnt[p] = 0;            // reset for next replay
    }
    if (tid == 0) { sth = -1; sccnt = 0; }
    hist[tid] = 0;
    __syncthreads();
    if (tid == 0) {
        int acc = 0;
        for (int c2 = 0; c2 < FG; c2++) { soff[c2] = acc; acc += scnt[c2]; }
        soff[FG] = acc;
    }
    __syncthreads();
    int L = soff[FG]; if (L > CAP) L = CAP;

    // warp w copies classes w, w+32, w+64
    for (int c2 = wid; c2 < FG; c2 += 32) {
        int off = soff[c2], cnt = scnt[c2];
        const unsigned long long* src = g_keys + (size_t)(b * FG + c2) * NN;
        for (int i = lane; i < cnt; i += 32) {
            int d = off + i;
            if (d < CAP) keys[d] = src[i];
        }
    }
    __syncthreads();

    // histogram on score top-16 bits (scores in (0.05,1) -> ~564 live bins)
    for (int i = tid; i < L; i += blockDim.x) {
        int bin = (int)(keys[i] >> 48) - BIN_BASE;
        bin = max(0, min(NB - 1, bin));
        atomicAdd(&hist[bin], 1);
    }
    __syncthreads();

    // suffix sum: hist[i] = #elements in bins >= i  (Hillis-Steele, 10 steps)
    #pragma unroll
    for (int d = 1; d < NB; d <<= 1) {
        int v = (tid + d < NB) ? hist[tid + d] : 0;
        __syncthreads();
        hist[tid] += v;
        __syncthreads();
    }

    // threshold bin: largest t with suffix(t) >= K
    if (hist[tid] >= KK && (tid == NB - 1 || hist[tid + 1] < KK)) sth = tid;
    __syncthreads();

    int t = sth;
    bool fast = (t >= 0) && (hist[t] <= CB);   // uniform across block

    const unsigned long long* srt;
    if (fast) {
        // collect bins >= t (count = suffix(t) <= CB)
        for (int i = tid; i < L; i += blockDim.x) {
            int bin = (int)(keys[i] >> 48) - BIN_BASE;
            bin = max(0, min(NB - 1, bin));
            if (bin >= t) {
                int pos = atomicAdd(&sccnt, 1);
                cbuf[pos] = keys[i];
            }
        }
        __syncthreads();
        int cnum = sccnt;
        int n2 = 128; while (n2 < cnum) n2 <<= 1;   // <= CB
        for (int i = cnum + tid; i < n2; i += blockDim.x) cbuf[i] = 0ull;
        __syncthreads();
        bitonic_desc(cbuf, n2, tid, blockDim.x);
        srt = cbuf;
    } else {
        // fallback: full sort (covers L < K and pathological tie bins)
        int n2 = 128; while (n2 < L) n2 <<= 1;
        for (int i = L + tid; i < n2; i += blockDim.x) keys[i] = 0ull;
        __syncthreads();
        bitonic_desc(keys, n2, tid, blockDim.x);
        srt = keys;
    }

    if (tid < KK) {
        int k = tid;
        unsigned long long key = srt[k];
        float sc = __uint_as_float((unsigned)(key >> 32));
        float x0 = 0.f, y0 = 0.f, x1 = 0.f, y1 = 0.f, scw = 0.f;
        int label = 0;
        if (sc > 0.0f) {
            unsigned fl = 0xFFFFFFFFu - (unsigned)(key & 0xFFFFFFFFull);
            int c2 = (int)(fl / NN), i = (int)(fl % NN);
            int base = (b * FG + c2) * NN + i;
            x0 = g_box[base*4+0]; y0 = g_box[base*4+1];
            x1 = g_box[base*4+2]; y1 = g_box[base*4+3];
            scw = sc; label = c2 + 1;
        }
        int bk = b * KK + k;
        out[bk*4+0] = x0; out[bk*4+1] = y0; out[bk*4+2] = x1; out[bk*4+3] = y1;
        out[BB*KK*4 + bk] = scw;                  // top_s at 3200
        out[BB*KK*4 + BB*KK + bk] = (float)label; // labels at 4000
        g_labels[bk] = label;
    }
}

// Per detection: gather its class channel of mask logits, sigmoid (float4-vectorized).
__global__ void k_mask(const float* __restrict__ ml, float* __restrict__ out) {
    int bk = blockIdx.x;                 // b*K + k
    int label = g_labels[bk];
    const float4* src = (const float4*)(ml + ((size_t)bk * CC + (size_t)label) * (MSZ*MSZ));
    float4* dst = (float4*)(out + (BB*KK*4 + 2*BB*KK) + (size_t)bk * (MSZ*MSZ));
    for (int t = threadIdx.x; t < (MSZ*MSZ)/4; t += blockDim.x) {
        float4 v = src[t];
        v.x = 1.0f / (1.0f + expf(-v.x));
        v.y = 1.0f / (1.0f + expf(-v.y));
        v.z = 1.0f / (1.0f + expf(-v.z));
        v.w = 1.0f / (1.0f + expf(-v.w));
        dst[t] = v;
    }
}

extern "C" void kernel_launch(void* const* d_in, const int* in_sizes, int n_in,
                              void* d_out, int out_size) {
    (void)in_sizes; (void)n_in; (void)out_size;
    const float* logits = (const float*)d_in[0];
    const float* reg    = (const float*)d_in[1];
    const float* props  = (const float*)d_in[2];
    const float* ml     = (const float*)d_in[3];
    float* out = (float*)d_out;

    k_softmax_cand<<<(BB*NN + 7) / 8, 256>>>(logits, reg, props);
    k_nms<<<NPROB, 256>>>();
    k_topk<<<BB, 1024>>>(out);
    k_mask<<<BB*KK, 196>>>(ml, out);
}